// round 4
// baseline (speedup 1.0000x reference)
#include <cuda_runtime.h>

#define BATCH 4
#define C1N 128
#define C2N 64
#define NPIX1 16384   // 128*128
#define NPIX2 65536   // 256*256
#define NB 256

// ---- scratch (device globals; zero-init at load; k_fuse re-zeroes g_gaps) ----
__device__ float g_gaps[BATCH * C1N + BATCH * C2N];  // [0,512): x1 sums, [512,768): x2 sums
__device__ float g_pos1[BATCH * NB * 64];            // [b][n][ij]
__device__ float g_pos2[BATCH * NB * 256];           // [b][n][ij]
__device__ float g_spa [BATCH * NPIX2];              // [b][h=n][w=k]
__device__ float g_w3t [BATCH * C2N * C2N];          // [b][c][o]  prefused, transposed
__device__ float g_s3  [C2N];
__device__ float g_t3  [C2N];

__device__ __forceinline__ float warpSum(float v) {
    #pragma unroll
    for (int o = 16; o; o >>= 1) v += __shfl_xor_sync(0xffffffffu, v, o);
    return v;
}

// ---- kernel 1: pos1 + x1 channel sums; warp owns 16 channels x 256 pixels ----
__global__ void __launch_bounds__(256) k_pos1(const float* __restrict__ x1,
                                              const float* __restrict__ wp,
                                              const float* __restrict__ bp) {
    __shared__ float part[8][256];
    int tid = threadIdx.x, wid = tid >> 5, lane = tid & 31;
    int b = blockIdx.x >> 6;
    int p0 = (blockIdx.x & 63) << 8;
    const float* plane = x1 + (size_t)b * C1N * NPIX1 + p0;

    float d[8];
    #pragma unroll
    for (int k = 0; k < 8; k++) d[k] = 0.f;

    #pragma unroll 4
    for (int j = 0; j < 16; j++) {
        int c = wid + 8 * j;                        // this warp's channel
        float w = __ldg(&wp[c]);
        const float4* cp = (const float4*)(plane + ((size_t)c << 14));
        float4 v0 = cp[lane];                       // pixels lane*4 .. +3
        float4 v1 = cp[lane + 32];                  // pixels 128+lane*4 .. +3
        d[0] = fmaf(w, v0.x, d[0]); d[1] = fmaf(w, v0.y, d[1]);
        d[2] = fmaf(w, v0.z, d[2]); d[3] = fmaf(w, v0.w, d[3]);
        d[4] = fmaf(w, v1.x, d[4]); d[5] = fmaf(w, v1.y, d[5]);
        d[6] = fmaf(w, v1.z, d[6]); d[7] = fmaf(w, v1.w, d[7]);
        float cs = ((v0.x + v0.y) + (v0.z + v0.w)) + ((v1.x + v1.y) + (v1.z + v1.w));
        cs = warpSum(cs);
        if (lane == 0) atomicAdd(&g_gaps[b * C1N + c], cs);
    }
    ((float4*)&part[wid][lane * 4])[0]       = make_float4(d[0], d[1], d[2], d[3]);
    ((float4*)&part[wid][128 + lane * 4])[0] = make_float4(d[4], d[5], d[6], d[7]);
    __syncthreads();

    float dot = bp[0];
    #pragma unroll
    for (int w = 0; w < 8; w++) dot += part[w][tid];
    int p = p0 + tid;
    int y = p >> 7, x = p & 127;
    int n  = ((y >> 3) << 4) | (x >> 3);
    int ij = ((y & 7) << 3) | (x & 7);
    g_pos1[((b << 8) | n) * 64 + ij] = dot;
}

// ---- kernel 2: pos2 + x2 channel sums; warp owns 8 channels x 256 pixels ----
__global__ void __launch_bounds__(256) k_pos2(const float* __restrict__ x2,
                                              const float* __restrict__ wp,
                                              const float* __restrict__ bp) {
    __shared__ float part[8][256];
    int tid = threadIdx.x, wid = tid >> 5, lane = tid & 31;
    int b = blockIdx.x >> 8;
    int p0 = (blockIdx.x & 255) << 8;
    const float* plane = x2 + (size_t)b * C2N * NPIX2 + p0;

    float d[8];
    #pragma unroll
    for (int k = 0; k < 8; k++) d[k] = 0.f;

    #pragma unroll
    for (int j = 0; j < 8; j++) {
        int c = wid + 8 * j;
        float w = __ldg(&wp[c]);
        const float4* cp = (const float4*)(plane + ((size_t)c << 16));
        float4 v0 = cp[lane];
        float4 v1 = cp[lane + 32];
        d[0] = fmaf(w, v0.x, d[0]); d[1] = fmaf(w, v0.y, d[1]);
        d[2] = fmaf(w, v0.z, d[2]); d[3] = fmaf(w, v0.w, d[3]);
        d[4] = fmaf(w, v1.x, d[4]); d[5] = fmaf(w, v1.y, d[5]);
        d[6] = fmaf(w, v1.z, d[6]); d[7] = fmaf(w, v1.w, d[7]);
        float cs = ((v0.x + v0.y) + (v0.z + v0.w)) + ((v1.x + v1.y) + (v1.z + v1.w));
        cs = warpSum(cs);
        if (lane == 0) atomicAdd(&g_gaps[BATCH * C1N + b * C2N + c], cs);
    }
    ((float4*)&part[wid][lane * 4])[0]       = make_float4(d[0], d[1], d[2], d[3]);
    ((float4*)&part[wid][128 + lane * 4])[0] = make_float4(d[4], d[5], d[6], d[7]);
    __syncthreads();

    float dot = bp[0];
    #pragma unroll
    for (int w = 0; w < 8; w++) dot += part[w][tid];
    int p = p0 + tid;
    int y = p >> 8, x = p & 255;
    int n  = ((y >> 4) << 4) | (x >> 4);
    int ij = ((y & 15) << 4) | (x & 15);
    g_pos2[((b << 8) | n) * 256 + ij] = dot;
}

// ---- kernel 3: mlp -> cw softmax (redundant per CTA) -> prefused w3t/s3/t3 ----
__global__ void __launch_bounds__(256) k_w3(const float* __restrict__ wc1, const float* __restrict__ bc1,
                                            const float* __restrict__ wc2, const float* __restrict__ bc2,
                                            const float* __restrict__ wf,  const float* __restrict__ bf,
                                            const float* __restrict__ gamma, const float* __restrict__ beta) {
    __shared__ float s_m1[256], s_m2[256], s_cw[256];
    int t = threadIdx.x;
    int b = t >> 6, g = (t >> 3) & 7, o = t & 7;
    const float INV1 = 1.f / NPIX1, INV2 = 1.f / NPIX2;
    {
        float a = bc1[o];
        const float* gp = &g_gaps[b * C1N + g * 16];
        #pragma unroll
        for (int c = 0; c < 16; c++) a = fmaf(wc1[o * 16 + c] * INV1, gp[c], a);
        s_m1[t] = fmaxf(a, 0.f);
    }
    {
        float a = bc2[o];
        const float* gp = &g_gaps[BATCH * C1N + b * C2N + g * 8];
        #pragma unroll
        for (int c = 0; c < 8; c++) a = fmaf(wc2[o * 8 + c] * INV2, gp[c], a);
        s_m2[t] = fmaxf(a, 0.f);
    }
    __syncthreads();
    if (t < 32) {
        int bb = t >> 3, gg = t & 7;
        int base = bb * 64 + gg * 8;
        float nr = 0.f;
        #pragma unroll
        for (int j = 0; j < 8; j++) { float m = s_m2[base + j]; nr += m * m; }
        float lg[8]; float mx = -1e30f;
        #pragma unroll
        for (int j = 0; j < 8; j++) { lg[j] = s_m1[base + j] * nr; mx = fmaxf(mx, lg[j]); }
        float Z = 0.f;
        #pragma unroll
        for (int j = 0; j < 8; j++) { lg[j] = expf(lg[j] - mx); Z += lg[j]; }
        float iz = 1.f / Z;
        #pragma unroll
        for (int j = 0; j < 8; j++) s_cw[base + j] = lg[j] * iz;
    }
    __syncthreads();
    const float A = rsqrtf(1.f + 1e-5f);
    #pragma unroll
    for (int k = 0; k < 4; k++) {            // this CTA's 1024-elem slice of [b][c][o]
        int i = blockIdx.x * 1024 + k * 256 + t;
        int bb = i >> 12, co = i & 4095, cc = co >> 6, oo = co & 63;
        g_w3t[i] = gamma[oo] * A * wf[oo * 64 + cc] * s_cw[bb * 64 + cc];
    }
    if (blockIdx.x == 0 && t < 64) {
        float ws = 0.f;
        for (int c = 0; c < 64; c++) ws += wf[t * 64 + c];
        float Ao = gamma[t] * A;
        g_s3[t] = Ao * ws;
        g_t3[t] = Ao * bf[t] + beta[t];
    }
}

// ---- kernel 4: per-block spatial attention (x1t register-hoisted, exp2) ----
__global__ void __launch_bounds__(256) k_spa(const float* __restrict__ wlin,
                                             const float* __restrict__ blin) {
    __shared__ float s_p1[64], s_x1t[256], s_p2[256], s_red[18];
    __shared__ float s_acc[8 * 256];
    const float LOG2E = 1.4426950408889634f;
    int tid = threadIdx.x, wid = tid >> 5, lane = tid & 31;
    int blk = blockIdx.x;                 // = b*256 + n
    if (tid < 64) s_p1[tid] = g_pos1[blk * 64 + tid];
    s_p2[tid] = g_pos2[blk * 256 + tid];
    __syncthreads();
    float acc_t = blin[tid];
    const float4* wr = (const float4*)(wlin + tid * 64);
    #pragma unroll
    for (int c4 = 0; c4 < 16; c4++) {
        float4 w = wr[c4];
        acc_t += w.x * s_p1[c4 * 4 + 0] + w.y * s_p1[c4 * 4 + 1]
               + w.z * s_p1[c4 * 4 + 2] + w.w * s_p1[c4 * 4 + 3];
    }
    acc_t *= LOG2E;                       // pre-scale: exp(z) = exp2(z*log2e)
    s_x1t[tid] = acc_t;
    float vmax = acc_t, vmin = acc_t;
    #pragma unroll
    for (int o = 16; o; o >>= 1) {
        vmax = fmaxf(vmax, __shfl_xor_sync(0xffffffffu, vmax, o));
        vmin = fminf(vmin, __shfl_xor_sync(0xffffffffu, vmin, o));
    }
    if (lane == 0) { s_red[wid] = vmax; s_red[8 + wid] = vmin; }
    __syncthreads();
    if (tid == 0) {
        float mx = s_red[0], mn = s_red[8];
        #pragma unroll
        for (int w = 1; w < 8; w++) { mx = fmaxf(mx, s_red[w]); mn = fminf(mn, s_red[8 + w]); }
        s_red[16] = mx; s_red[17] = mn;
    }
    __syncthreads();
    float xmax = s_red[16], xmin = s_red[17];

    float x1r[8];                         // lane's 8 columns, loop-invariant
    #pragma unroll
    for (int j = 0; j < 8; j++) x1r[j] = s_x1t[lane + 32 * j];

    float accl[8];
    #pragma unroll
    for (int j = 0; j < 8; j++) accl[j] = 0.f;

    for (int q = wid; q < 256; q += 8) {
        float p = s_p2[q];
        float rm = (p >= 0.f) ? p * xmax : p * xmin;   // exact row max (log2 domain)
        float e[8]; float sum = 0.f;
        #pragma unroll
        for (int j = 0; j < 8; j++) {
            float v = exp2f(fmaf(p, x1r[j], -rm));
            e[j] = v; sum += v;
        }
        #pragma unroll
        for (int o = 16; o; o >>= 1) sum += __shfl_xor_sync(0xffffffffu, sum, o);
        float coef = __fdividef(p, sum);
        #pragma unroll
        for (int j = 0; j < 8; j++) accl[j] = fmaf(coef, e[j], accl[j]);
    }
    #pragma unroll
    for (int j = 0; j < 8; j++) s_acc[wid * 256 + lane + 32 * j] = accl[j];
    __syncthreads();
    float v = 0.f;
    #pragma unroll
    for (int w = 0; w < 8; w++) v += s_acc[w * 256 + tid];
    g_spa[blk * 256 + tid] = v;
}

// ---- kernel 5: fused 1x1 conv + BN + ReLU with packed f32x2 FMA ----
__global__ void __launch_bounds__(256) k_fuse(const float* __restrict__ x2,
                                              float* __restrict__ out) {
    __shared__ float s_w[C2N * C2N];   // [c][o] (g_w3t already transposed)
    __shared__ float s_s3[64], s_t3[64];
    int tid = threadIdx.x;
    int b = blockIdx.x >> 8;
    int p = ((blockIdx.x & 255) << 8) | tid;

    // re-zero the gap accumulators for the next graph replay
    if (blockIdx.x < 3) {
        int i = blockIdx.x * 256 + tid;
        if (i < BATCH * C1N + BATCH * C2N) g_gaps[i] = 0.f;
    }

    const float4* gw = (const float4*)&g_w3t[b * 4096];
    float4* swv = (float4*)s_w;
    for (int i = tid; i < 1024; i += 256) swv[i] = gw[i];
    if (tid < 64) { s_s3[tid] = g_s3[tid]; s_t3[tid] = g_t3[tid]; }
    __syncthreads();

    unsigned long long acc[32];
    #pragma unroll
    for (int j = 0; j < 32; j++) acc[j] = 0ull;

    const float* xb = x2 + (size_t)b * C2N * NPIX2 + p;
    for (int c = 0; c < 64; c++) {
        float xv = xb[(size_t)c << 16];
        unsigned long long xv2;
        asm("mov.b64 %0, {%1, %1};" : "=l"(xv2) : "f"(xv));
        const ulonglong2* wc = (const ulonglong2*)&s_w[c << 6];
        #pragma unroll
        for (int j = 0; j < 16; j++) {
            ulonglong2 w = wc[j];
            asm("fma.rn.f32x2 %0, %1, %2, %0;" : "+l"(acc[2 * j + 0]) : "l"(w.x), "l"(xv2));
            asm("fma.rn.f32x2 %0, %1, %2, %0;" : "+l"(acc[2 * j + 1]) : "l"(w.y), "l"(xv2));
        }
    }
    float sv = g_spa[(size_t)b * NPIX2 + p];
    float* ob = out + (size_t)b * C2N * NPIX2 + p;
    #pragma unroll
    for (int j = 0; j < 32; j++) {
        float lo, hi;
        asm("mov.b64 {%0, %1}, %2;" : "=f"(lo), "=f"(hi) : "l"(acc[j]));
        int o = 2 * j;
        float r0 = fmaf(s_s3[o + 0], sv, lo) + s_t3[o + 0];
        float r1 = fmaf(s_s3[o + 1], sv, hi) + s_t3[o + 1];
        ob[(size_t)(o + 0) << 16] = fmaxf(r0, 0.f);
        ob[(size_t)(o + 1) << 16] = fmaxf(r1, 0.f);
    }
}

extern "C" void kernel_launch(void* const* d_in, const int* in_sizes, int n_in,
                              void* d_out, int out_size) {
    const float* x1    = (const float*)d_in[0];
    const float* x2    = (const float*)d_in[1];
    const float* wc1   = (const float*)d_in[2];
    const float* bc1   = (const float*)d_in[3];
    const float* wc2   = (const float*)d_in[4];
    const float* bc2   = (const float*)d_in[5];
    const float* wp1   = (const float*)d_in[6];
    const float* bp1   = (const float*)d_in[7];
    const float* wp2   = (const float*)d_in[8];
    const float* bp2   = (const float*)d_in[9];
    const float* wlin  = (const float*)d_in[10];
    const float* blin  = (const float*)d_in[11];
    const float* wf    = (const float*)d_in[12];
    const float* bf    = (const float*)d_in[13];
    const float* gamma = (const float*)d_in[14];
    const float* beta  = (const float*)d_in[15];
    float* out = (float*)d_out;

    k_pos1<<<BATCH * NPIX1 / 256, 256>>>(x1, wp1, bp1);
    k_pos2<<<BATCH * NPIX2 / 256, 256>>>(x2, wp2, bp2);
    k_w3  <<<16, 256>>>(wc1, bc1, wc2, bc2, wf, bf, gamma, beta);
    k_spa <<<BATCH * NB, 256>>>(wlin, blin);
    k_fuse<<<BATCH * NPIX2 / 256, 256>>>(x2, out);
}

// round 6
// speedup vs baseline: 1.0328x; 1.0328x over previous
#include <cuda_runtime.h>

#define BATCH 4
#define C1N 128
#define C2N 64
#define NPIX1 16384   // 128*128
#define NPIX2 65536   // 256*256
#define NB 256

// ---- scratch (device globals; zero-init at load; k_spafuse re-zeroes g_gaps) ----
__device__ float g_gaps[BATCH * C1N + BATCH * C2N];  // [0,512): x1 sums, [512,768): x2 sums
__device__ float g_pos1[BATCH * NB * 64];            // [b][n][ij]
__device__ float g_pos2[BATCH * NB * 256];           // [b][n][ij]
__device__ float g_w3t [BATCH * C2N * C2N];          // [b][c][o]  prefused, transposed
__device__ float g_s3  [C2N];
__device__ float g_t3  [C2N];

__device__ __forceinline__ float warpSum(float v) {
    #pragma unroll
    for (int o = 16; o; o >>= 1) v += __shfl_xor_sync(0xffffffffu, v, o);
    return v;
}
__device__ __forceinline__ float ex2f(float x) {   // guaranteed MUFU.EX2
    float r;
    asm("ex2.approx.ftz.f32 %0, %1;" : "=f"(r) : "f"(x));
    return r;
}

// ---- kernel 1: pos1 & pos2 + channel sums in ONE launch ----
__global__ void __launch_bounds__(256) k_pos(const float* __restrict__ x1,
                                             const float* __restrict__ wp1,
                                             const float* __restrict__ bp1,
                                             const float* __restrict__ x2,
                                             const float* __restrict__ wp2,
                                             const float* __restrict__ bp2) {
    __shared__ float part[8][256];
    int tid = threadIdx.x, wid = tid >> 5, lane = tid & 31;

    if (blockIdx.x < 256) {
        // ---- pos1: warp owns 16 channels x 256 pixels ----
        int bid = blockIdx.x;
        int b = bid >> 6;
        int p0 = (bid & 63) << 8;
        const float* plane = x1 + (size_t)b * C1N * NPIX1 + p0;
        float d[8];
        #pragma unroll
        for (int k = 0; k < 8; k++) d[k] = 0.f;
        #pragma unroll 4
        for (int j = 0; j < 16; j++) {
            int c = wid + 8 * j;
            float w = __ldg(&wp1[c]);
            const float4* cp = (const float4*)(plane + ((size_t)c << 14));
            float4 v0 = cp[lane];
            float4 v1 = cp[lane + 32];
            d[0] = fmaf(w, v0.x, d[0]); d[1] = fmaf(w, v0.y, d[1]);
            d[2] = fmaf(w, v0.z, d[2]); d[3] = fmaf(w, v0.w, d[3]);
            d[4] = fmaf(w, v1.x, d[4]); d[5] = fmaf(w, v1.y, d[5]);
            d[6] = fmaf(w, v1.z, d[6]); d[7] = fmaf(w, v1.w, d[7]);
            float cs = ((v0.x + v0.y) + (v0.z + v0.w)) + ((v1.x + v1.y) + (v1.z + v1.w));
            cs = warpSum(cs);
            if (lane == 0) atomicAdd(&g_gaps[b * C1N + c], cs);
        }
        ((float4*)&part[wid][lane * 4])[0]       = make_float4(d[0], d[1], d[2], d[3]);
        ((float4*)&part[wid][128 + lane * 4])[0] = make_float4(d[4], d[5], d[6], d[7]);
        __syncthreads();
        float dot = bp1[0];
        #pragma unroll
        for (int w = 0; w < 8; w++) dot += part[w][tid];
        int p = p0 + tid;
        int y = p >> 7, x = p & 127;
        int n  = ((y >> 3) << 4) | (x >> 3);
        int ij = ((y & 7) << 3) | (x & 7);
        g_pos1[((b << 8) | n) * 64 + ij] = dot;
    } else {
        // ---- pos2: warp owns 8 channels x 256 pixels ----
        int bid = blockIdx.x - 256;
        int b = bid >> 8;
        int p0 = (bid & 255) << 8;
        const float* plane = x2 + (size_t)b * C2N * NPIX2 + p0;
        float d[8];
        #pragma unroll
        for (int k = 0; k < 8; k++) d[k] = 0.f;
        #pragma unroll
        for (int j = 0; j < 8; j++) {
            int c = wid + 8 * j;
            float w = __ldg(&wp2[c]);
            const float4* cp = (const float4*)(plane + ((size_t)c << 16));
            float4 v0 = cp[lane];
            float4 v1 = cp[lane + 32];
            d[0] = fmaf(w, v0.x, d[0]); d[1] = fmaf(w, v0.y, d[1]);
            d[2] = fmaf(w, v0.z, d[2]); d[3] = fmaf(w, v0.w, d[3]);
            d[4] = fmaf(w, v1.x, d[4]); d[5] = fmaf(w, v1.y, d[5]);
            d[6] = fmaf(w, v1.z, d[6]); d[7] = fmaf(w, v1.w, d[7]);
            float cs = ((v0.x + v0.y) + (v0.z + v0.w)) + ((v1.x + v1.y) + (v1.z + v1.w));
            cs = warpSum(cs);
            if (lane == 0) atomicAdd(&g_gaps[BATCH * C1N + b * C2N + c], cs);
        }
        ((float4*)&part[wid][lane * 4])[0]       = make_float4(d[0], d[1], d[2], d[3]);
        ((float4*)&part[wid][128 + lane * 4])[0] = make_float4(d[4], d[5], d[6], d[7]);
        __syncthreads();
        float dot = bp2[0];
        #pragma unroll
        for (int w = 0; w < 8; w++) dot += part[w][tid];
        int p = p0 + tid;
        int y = p >> 8, x = p & 255;
        int n  = ((y >> 4) << 4) | (x >> 4);
        int ij = ((y & 15) << 4) | (x & 15);
        g_pos2[((b << 8) | n) * 256 + ij] = dot;
    }
}

// ---- kernel 2: mlp -> cw softmax (redundant per CTA) -> prefused w3t/s3/t3 ----
__global__ void __launch_bounds__(256) k_w3(const float* __restrict__ wc1, const float* __restrict__ bc1,
                                            const float* __restrict__ wc2, const float* __restrict__ bc2,
                                            const float* __restrict__ wf,  const float* __restrict__ bf,
                                            const float* __restrict__ gamma, const float* __restrict__ beta) {
    __shared__ float s_m1[256], s_m2[256], s_cw[256];
    int t = threadIdx.x;
    int b = t >> 6, g = (t >> 3) & 7, o = t & 7;
    const float INV1 = 1.f / NPIX1, INV2 = 1.f / NPIX2;
    {
        float a = bc1[o];
        const float* gp = &g_gaps[b * C1N + g * 16];
        #pragma unroll
        for (int c = 0; c < 16; c++) a = fmaf(wc1[o * 16 + c] * INV1, gp[c], a);
        s_m1[t] = fmaxf(a, 0.f);
    }
    {
        float a = bc2[o];
        const float* gp = &g_gaps[BATCH * C1N + b * C2N + g * 8];
        #pragma unroll
        for (int c = 0; c < 8; c++) a = fmaf(wc2[o * 8 + c] * INV2, gp[c], a);
        s_m2[t] = fmaxf(a, 0.f);
    }
    __syncthreads();
    if (t < 32) {
        int bb = t >> 3, gg = t & 7;
        int base = bb * 64 + gg * 8;
        float nr = 0.f;
        #pragma unroll
        for (int j = 0; j < 8; j++) { float m = s_m2[base + j]; nr += m * m; }
        float lg[8]; float mx = -1e30f;
        #pragma unroll
        for (int j = 0; j < 8; j++) { lg[j] = s_m1[base + j] * nr; mx = fmaxf(mx, lg[j]); }
        float Z = 0.f;
        #pragma unroll
        for (int j = 0; j < 8; j++) { lg[j] = expf(lg[j] - mx); Z += lg[j]; }
        float iz = 1.f / Z;
        #pragma unroll
        for (int j = 0; j < 8; j++) s_cw[base + j] = lg[j] * iz;
    }
    __syncthreads();
    const float A = rsqrtf(1.f + 1e-5f);
    #pragma unroll
    for (int k = 0; k < 4; k++) {            // this CTA's 1024-elem slice of [b][c][o]
        int i = blockIdx.x * 1024 + k * 256 + t;
        int bb = i >> 12, co = i & 4095, cc = co >> 6, oo = co & 63;
        g_w3t[i] = gamma[oo] * A * wf[oo * 64 + cc] * s_cw[bb * 64 + cc];
    }
    if (blockIdx.x == 0 && t < 64) {
        float ws = 0.f;
        for (int c = 0; c < 64; c++) ws += wf[t * 64 + c];
        float Ao = gamma[t] * A;
        g_s3[t] = Ao * ws;
        g_t3[t] = Ao * bf[t] + beta[t];
    }
}

// ---- kernel 3: spatial attention + fused conv/BN/ReLU for one output row ----
// CTA = b*256 + n: spa block n produces exactly output image row n.
__global__ void __launch_bounds__(256) k_spafuse(const float* __restrict__ wlin,
                                                 const float* __restrict__ blin,
                                                 const float* __restrict__ x2,
                                                 float* __restrict__ out) {
    __shared__ float s_w[C2N * C2N];             // fuse weights [c][o]
    __shared__ float s_p1[64], s_x1t[256], s_p2[256], s_red[18];
    __shared__ float s_acc[8 * 256];
    __shared__ float s_spa[256];
    __shared__ float s_s3[64], s_t3[64];
    const float LOG2E = 1.4426950408889634f;
    int tid = threadIdx.x, wid = tid >> 5, lane = tid & 31;
    int blk = blockIdx.x;                 // b*256 + n
    int b = blk >> 8;

    // re-zero the gap accumulators for the next graph replay (w3 already consumed them)
    if (blk < 3) {
        int i = blk * 256 + tid;
        if (i < BATCH * C1N + BATCH * C2N) g_gaps[i] = 0.f;
    }

    // prefetch fuse weights while spa phase runs
    {
        const float4* gw = (const float4*)&g_w3t[b * 4096];
        float4* swv = (float4*)s_w;
        #pragma unroll
        for (int k = 0; k < 4; k++) swv[k * 256 + tid] = gw[k * 256 + tid];
        if (tid < 64) { s_s3[tid] = g_s3[tid]; s_t3[tid] = g_t3[tid]; }
    }

    // ---- phase A: spatial attention for block n ----
    if (tid < 64) s_p1[tid] = g_pos1[blk * 64 + tid];
    s_p2[tid] = g_pos2[blk * 256 + tid];
    __syncthreads();
    float acc_t = blin[tid];
    const float4* wr = (const float4*)(wlin + tid * 64);
    #pragma unroll
    for (int c4 = 0; c4 < 16; c4++) {
        float4 w = wr[c4];
        acc_t += w.x * s_p1[c4 * 4 + 0] + w.y * s_p1[c4 * 4 + 1]
               + w.z * s_p1[c4 * 4 + 2] + w.w * s_p1[c4 * 4 + 3];
    }
    acc_t *= LOG2E;                       // exp(z) = exp2(z*log2e)
    s_x1t[tid] = acc_t;
    float vmax = acc_t, vmin = acc_t;
    #pragma unroll
    for (int o = 16; o; o >>= 1) {
        vmax = fmaxf(vmax, __shfl_xor_sync(0xffffffffu, vmax, o));
        vmin = fminf(vmin, __shfl_xor_sync(0xffffffffu, vmin, o));
    }
    if (lane == 0) { s_red[wid] = vmax; s_red[8 + wid] = vmin; }
    __syncthreads();
    if (tid == 0) {
        float mx = s_red[0], mn = s_red[8];
        #pragma unroll
        for (int w = 1; w < 8; w++) { mx = fmaxf(mx, s_red[w]); mn = fminf(mn, s_red[8 + w]); }
        s_red[16] = mx; s_red[17] = mn;
    }
    __syncthreads();
    float xmax = s_red[16], xmin = s_red[17];

    float x1r[8];
    #pragma unroll
    for (int j = 0; j < 8; j++) x1r[j] = s_x1t[lane + 32 * j];

    float accl[8];
    #pragma unroll
    for (int j = 0; j < 8; j++) accl[j] = 0.f;

    #pragma unroll 2
    for (int q = wid; q < 256; q += 8) {
        float p = s_p2[q];
        float rm = (p >= 0.f) ? p * xmax : p * xmin;   // exact row max (log2 domain)
        float e[8]; float sum = 0.f;
        #pragma unroll
        for (int j = 0; j < 8; j++) {
            float v = ex2f(fmaf(p, x1r[j], -rm));      // single MUFU.EX2
            e[j] = v; sum += v;
        }
        #pragma unroll
        for (int o = 16; o; o >>= 1) sum += __shfl_xor_sync(0xffffffffu, sum, o);
        float coef = __fdividef(p, sum);
        #pragma unroll
        for (int j = 0; j < 8; j++) accl[j] = fmaf(coef, e[j], accl[j]);
    }
    #pragma unroll
    for (int j = 0; j < 8; j++) s_acc[wid * 256 + lane + 32 * j] = accl[j];
    __syncthreads();
    {
        float v = 0.f;
        #pragma unroll
        for (int w = 0; w < 8; w++) v += s_acc[w * 256 + tid];
        s_spa[tid] = v;                   // stays in smem — no global round-trip
    }
    __syncthreads();

    // ---- phase B: fused 1x1 conv + BN + ReLU for pixel (row n, col tid) ----
    int p = (blk & 255) * 256 + tid;      // pixel within batch plane
    unsigned long long acc[32];
    #pragma unroll
    for (int j = 0; j < 32; j++) acc[j] = 0ull;

    const float* xb = x2 + (size_t)b * C2N * NPIX2 + p;
    for (int c = 0; c < 64; c++) {
        float xv = xb[(size_t)c << 16];
        unsigned long long xv2;
        asm("mov.b64 %0, {%1, %1};" : "=l"(xv2) : "f"(xv));
        const ulonglong2* wc = (const ulonglong2*)&s_w[c << 6];
        #pragma unroll
        for (int j = 0; j < 16; j++) {
            ulonglong2 w = wc[j];
            asm("fma.rn.f32x2 %0, %1, %2, %0;" : "+l"(acc[2 * j + 0]) : "l"(w.x), "l"(xv2));
            asm("fma.rn.f32x2 %0, %1, %2, %0;" : "+l"(acc[2 * j + 1]) : "l"(w.y), "l"(xv2));
        }
    }
    float sv = s_spa[tid];
    float* ob = out + (size_t)b * C2N * NPIX2 + p;
    #pragma unroll
    for (int j = 0; j < 32; j++) {
        float lo, hi;
        asm("mov.b64 {%0, %1}, %2;" : "=f"(lo), "=f"(hi) : "l"(acc[j]));
        int o = 2 * j;
        float r0 = fmaf(s_s3[o + 0], sv, lo) + s_t3[o + 0];
        float r1 = fmaf(s_s3[o + 1], sv, hi) + s_t3[o + 1];
        ob[(size_t)(o + 0) << 16] = fmaxf(r0, 0.f);
        ob[(size_t)(o + 1) << 16] = fmaxf(r1, 0.f);
    }
}

extern "C" void kernel_launch(void* const* d_in, const int* in_sizes, int n_in,
                              void* d_out, int out_size) {
    const float* x1    = (const float*)d_in[0];
    const float* x2    = (const float*)d_in[1];
    const float* wc1   = (const float*)d_in[2];
    const float* bc1   = (const float*)d_in[3];
    const float* wc2   = (const float*)d_in[4];
    const float* bc2   = (const float*)d_in[5];
    const float* wp1   = (const float*)d_in[6];
    const float* bp1   = (const float*)d_in[7];
    const float* wp2   = (const float*)d_in[8];
    const float* bp2   = (const float*)d_in[9];
    const float* wlin  = (const float*)d_in[10];
    const float* blin  = (const float*)d_in[11];
    const float* wf    = (const float*)d_in[12];
    const float* bf    = (const float*)d_in[13];
    const float* gamma = (const float*)d_in[14];
    const float* beta  = (const float*)d_in[15];
    float* out = (float*)d_out;

    k_pos    <<<256 + 1024, 256>>>(x1, wp1, bp1, x2, wp2, bp2);
    k_w3     <<<16, 256>>>(wc1, bc1, wc2, bc2, wf, bf, gamma, beta);
    k_spafuse<<<BATCH * NB, 256>>>(wlin, blin, x2, out);
}

// round 8
// speedup vs baseline: 1.0985x; 1.0635x over previous
#include <cuda_runtime.h>

#define BATCH 4
#define C1N 128
#define C2N 64
#define NPIX1 16384   // 128*128
#define NPIX2 65536   // 256*256
#define NB 256

// ---- scratch (device globals; zero-init at load; k_spafuse re-zeroes g_gaps) ----
__device__ float g_gaps[BATCH * C1N + BATCH * C2N];  // [0,512): x1 sums, [512,768): x2 sums
__device__ __align__(16) float g_pos1[BATCH * NB * 64];   // [b][n][ij]
__device__ __align__(16) float g_pos2[BATCH * NB * 256];  // [b][n][ij]
__device__ __align__(16) float g_w3t [BATCH * C2N * C2N]; // [b][c][o]  prefused, transposed
__device__ __align__(16) float g_s3  [C2N];
__device__ __align__(16) float g_t3  [C2N];

__device__ __forceinline__ float ex2f(float x) {   // guaranteed MUFU.EX2
    float r;
    asm("ex2.approx.ftz.f32 %0, %1;" : "=f"(r) : "f"(x));
    return r;
}

// ---- kernel 1: pos1 & pos2 + channel sums; NO in-loop reductions ----
__global__ void __launch_bounds__(256) k_pos(const float* __restrict__ x1,
                                             const float* __restrict__ wp1,
                                             const float* __restrict__ bp1,
                                             const float* __restrict__ x2,
                                             const float* __restrict__ wp2,
                                             const float* __restrict__ bp2) {
    __shared__ __align__(16) float part[8][256];
    __shared__ float cpart[8][16][33];   // padded: conflict-free column reads
    int tid = threadIdx.x, wid = tid >> 5, lane = tid & 31;

    if (blockIdx.x < 256) {
        // ---- pos1: warp owns 16 channels x 256 pixels ----
        int bid = blockIdx.x;
        int b = bid >> 6;
        int p0 = (bid & 63) << 8;
        const float* plane = x1 + (size_t)b * C1N * NPIX1 + p0;
        float d[8];
        #pragma unroll
        for (int k = 0; k < 8; k++) d[k] = 0.f;
        float cs[16];
        #pragma unroll 8
        for (int j = 0; j < 16; j++) {
            int c = wid + 8 * j;
            float w = __ldg(&wp1[c]);
            const float4* cp = (const float4*)(plane + ((size_t)c << 14));
            float4 v0 = cp[lane];
            float4 v1 = cp[lane + 32];
            d[0] = fmaf(w, v0.x, d[0]); d[1] = fmaf(w, v0.y, d[1]);
            d[2] = fmaf(w, v0.z, d[2]); d[3] = fmaf(w, v0.w, d[3]);
            d[4] = fmaf(w, v1.x, d[4]); d[5] = fmaf(w, v1.y, d[5]);
            d[6] = fmaf(w, v1.z, d[6]); d[7] = fmaf(w, v1.w, d[7]);
            cs[j] = ((v0.x + v0.y) + (v0.z + v0.w)) + ((v1.x + v1.y) + (v1.z + v1.w));
        }
        #pragma unroll
        for (int j = 0; j < 16; j++) cpart[wid][j][lane] = cs[j];
        ((float4*)&part[wid][lane * 4])[0]       = make_float4(d[0], d[1], d[2], d[3]);
        ((float4*)&part[wid][128 + lane * 4])[0] = make_float4(d[4], d[5], d[6], d[7]);
        __syncthreads();
        float dot = bp1[0];
        #pragma unroll
        for (int w = 0; w < 8; w++) dot += part[w][tid];
        int p = p0 + tid;
        int y = p >> 7, x = p & 127;
        int n  = ((y >> 3) << 4) | (x >> 3);
        int ij = ((y & 7) << 3) | (x & 7);
        g_pos1[((b << 8) | n) * 64 + ij] = dot;
        if (tid < 128) {                 // channel-sum reduce: thread owns (warp, j)
            int w = tid >> 4, j = tid & 15;
            float s = 0.f;
            #pragma unroll
            for (int l = 0; l < 32; l++) s += cpart[w][j][l];
            atomicAdd(&g_gaps[b * C1N + w + 8 * j], s);
        }
    } else {
        // ---- pos2: warp owns 8 channels x 256 pixels ----
        int bid = blockIdx.x - 256;
        int b = bid >> 8;
        int p0 = (bid & 255) << 8;
        const float* plane = x2 + (size_t)b * C2N * NPIX2 + p0;
        float d[8];
        #pragma unroll
        for (int k = 0; k < 8; k++) d[k] = 0.f;
        float cs[8];
        #pragma unroll
        for (int j = 0; j < 8; j++) {
            int c = wid + 8 * j;
            float w = __ldg(&wp2[c]);
            const float4* cp = (const float4*)(plane + ((size_t)c << 16));
            float4 v0 = cp[lane];
            float4 v1 = cp[lane + 32];
            d[0] = fmaf(w, v0.x, d[0]); d[1] = fmaf(w, v0.y, d[1]);
            d[2] = fmaf(w, v0.z, d[2]); d[3] = fmaf(w, v0.w, d[3]);
            d[4] = fmaf(w, v1.x, d[4]); d[5] = fmaf(w, v1.y, d[5]);
            d[6] = fmaf(w, v1.z, d[6]); d[7] = fmaf(w, v1.w, d[7]);
            cs[j] = ((v0.x + v0.y) + (v0.z + v0.w)) + ((v1.x + v1.y) + (v1.z + v1.w));
        }
        #pragma unroll
        for (int j = 0; j < 8; j++) cpart[wid][j][lane] = cs[j];
        ((float4*)&part[wid][lane * 4])[0]       = make_float4(d[0], d[1], d[2], d[3]);
        ((float4*)&part[wid][128 + lane * 4])[0] = make_float4(d[4], d[5], d[6], d[7]);
        __syncthreads();
        float dot = bp2[0];
        #pragma unroll
        for (int w = 0; w < 8; w++) dot += part[w][tid];
        int p = p0 + tid;
        int y = p >> 8, x = p & 255;
        int n  = ((y >> 4) << 4) | (x >> 4);
        int ij = ((y & 15) << 4) | (x & 15);
        g_pos2[((b << 8) | n) * 256 + ij] = dot;
        if (tid < 64) {
            int w = tid >> 3, j = tid & 7;
            float s = 0.f;
            #pragma unroll
            for (int l = 0; l < 32; l++) s += cpart[w][j][l];
            atomicAdd(&g_gaps[BATCH * C1N + b * C2N + w + 8 * j], s);
        }
    }
}

// ---- kernel 2: mlp -> cw softmax (redundant per CTA) -> prefused w3t/s3/t3 ----
__global__ void __launch_bounds__(256) k_w3(const float* __restrict__ wc1, const float* __restrict__ bc1,
                                            const float* __restrict__ wc2, const float* __restrict__ bc2,
                                            const float* __restrict__ wf,  const float* __restrict__ bf,
                                            const float* __restrict__ gamma, const float* __restrict__ beta) {
    __shared__ float s_m1[256], s_m2[256], s_cw[256];
    int t = threadIdx.x;
    int b = t >> 6, g = (t >> 3) & 7, o = t & 7;
    const float INV1 = 1.f / NPIX1, INV2 = 1.f / NPIX2;
    {
        float a = bc1[o];
        const float* gp = &g_gaps[b * C1N + g * 16];
        #pragma unroll
        for (int c = 0; c < 16; c++) a = fmaf(wc1[o * 16 + c] * INV1, gp[c], a);
        s_m1[t] = fmaxf(a, 0.f);
    }
    {
        float a = bc2[o];
        const float* gp = &g_gaps[BATCH * C1N + b * C2N + g * 8];
        #pragma unroll
        for (int c = 0; c < 8; c++) a = fmaf(wc2[o * 8 + c] * INV2, gp[c], a);
        s_m2[t] = fmaxf(a, 0.f);
    }
    __syncthreads();
    if (t < 32) {
        int bb = t >> 3, gg = t & 7;
        int base = bb * 64 + gg * 8;
        float nr = 0.f;
        #pragma unroll
        for (int j = 0; j < 8; j++) { float m = s_m2[base + j]; nr += m * m; }
        float lg[8]; float mx = -1e30f;
        #pragma unroll
        for (int j = 0; j < 8; j++) { lg[j] = s_m1[base + j] * nr; mx = fmaxf(mx, lg[j]); }
        float Z = 0.f;
        #pragma unroll
        for (int j = 0; j < 8; j++) { lg[j] = expf(lg[j] - mx); Z += lg[j]; }
        float iz = 1.f / Z;
        #pragma unroll
        for (int j = 0; j < 8; j++) s_cw[base + j] = lg[j] * iz;
    }
    __syncthreads();
    const float A = rsqrtf(1.f + 1e-5f);
    #pragma unroll
    for (int k = 0; k < 4; k++) {            // this CTA's 1024-elem slice of [b][c][o]
        int i = blockIdx.x * 1024 + k * 256 + t;
        int bb = i >> 12, co = i & 4095, cc = co >> 6, oo = co & 63;
        g_w3t[i] = gamma[oo] * A * wf[oo * 64 + cc] * s_cw[bb * 64 + cc];
    }
    if (blockIdx.x == 0 && t < 64) {
        float ws = 0.f;
        for (int c = 0; c < 64; c++) ws += wf[t * 64 + c];
        float Ao = gamma[t] * A;
        g_s3[t] = Ao * ws;
        g_t3[t] = Ao * bf[t] + beta[t];
    }
}

// ---- kernel 3: spatial attention + fused conv/BN/ReLU for one output row ----
// CTA = b*256 + n. Fuse phase: thread = (opart 0..3, pixg 0..63) -> 16 outputs x 4 pixels.
__global__ void __launch_bounds__(256) k_spafuse(const float* __restrict__ wlin,
                                                 const float* __restrict__ blin,
                                                 const float* __restrict__ x2,
                                                 float* __restrict__ out) {
    __shared__ __align__(16) float s_w[C2N * C2N];   // fuse weights [c][o]
    __shared__ __align__(16) float s_spa[256];
    __shared__ __align__(16) float s_p1[64];
    __shared__ float s_x1t[256], s_p2[256], s_red[18];
    __shared__ float s_acc[8 * 256];
    __shared__ float s_s3[64], s_t3[64];
    const float LOG2E = 1.4426950408889634f;
    int tid = threadIdx.x, wid = tid >> 5, lane = tid & 31;
    int blk = blockIdx.x;                 // b*256 + n
    int b = blk >> 8;

    // re-zero the gap accumulators for the next graph replay
    if (blk < 3) {
        int i = blk * 256 + tid;
        if (i < BATCH * C1N + BATCH * C2N) g_gaps[i] = 0.f;
    }

    // prefetch fuse weights while spa phase runs
    {
        const float4* gw = (const float4*)&g_w3t[b * 4096];
        float4* swv = (float4*)s_w;
        #pragma unroll
        for (int k = 0; k < 4; k++) swv[k * 256 + tid] = gw[k * 256 + tid];
        if (tid < 64) { s_s3[tid] = g_s3[tid]; s_t3[tid] = g_t3[tid]; }
    }

    // ---- phase A: spatial attention for block n ----
    if (tid < 64) s_p1[tid] = g_pos1[blk * 64 + tid];
    s_p2[tid] = g_pos2[blk * 256 + tid];
    __syncthreads();
    float acc_t = blin[tid];
    const float4* wr = (const float4*)(wlin + tid * 64);
    #pragma unroll
    for (int c4 = 0; c4 < 16; c4++) {
        float4 w = wr[c4];
        acc_t += w.x * s_p1[c4 * 4 + 0] + w.y * s_p1[c4 * 4 + 1]
               + w.z * s_p1[c4 * 4 + 2] + w.w * s_p1[c4 * 4 + 3];
    }
    acc_t *= LOG2E;                       // exp(z) = exp2(z*log2e)
    s_x1t[tid] = acc_t;
    float vmax = acc_t, vmin = acc_t;
    #pragma unroll
    for (int o = 16; o; o >>= 1) {
        vmax = fmaxf(vmax, __shfl_xor_sync(0xffffffffu, vmax, o));
        vmin = fminf(vmin, __shfl_xor_sync(0xffffffffu, vmin, o));
    }
    if (lane == 0) { s_red[wid] = vmax; s_red[8 + wid] = vmin; }
    __syncthreads();
    if (tid == 0) {
        float mx = s_red[0], mn = s_red[8];
        #pragma unroll
        for (int w = 1; w < 8; w++) { mx = fmaxf(mx, s_red[w]); mn = fminf(mn, s_red[8 + w]); }
        s_red[16] = mx; s_red[17] = mn;
    }
    __syncthreads();
    float xmax = s_red[16], xmin = s_red[17];

    float x1r[8];
    #pragma unroll
    for (int j = 0; j < 8; j++) x1r[j] = s_x1t[lane + 32 * j];

    float accl[8];
    #pragma unroll
    for (int j = 0; j < 8; j++) accl[j] = 0.f;

    #pragma unroll 2
    for (int q = wid; q < 256; q += 8) {
        float p = s_p2[q];
        float rm = (p >= 0.f) ? p * xmax : p * xmin;   // exact row max (log2 domain)
        float e[8]; float sum = 0.f;
        #pragma unroll
        for (int j = 0; j < 8; j++) {
            float v = ex2f(fmaf(p, x1r[j], -rm));      // single MUFU.EX2
            e[j] = v; sum += v;
        }
        #pragma unroll
        for (int o = 16; o; o >>= 1) sum += __shfl_xor_sync(0xffffffffu, sum, o);
        float coef = __fdividef(p, sum);
        #pragma unroll
        for (int j = 0; j < 8; j++) accl[j] = fmaf(coef, e[j], accl[j]);
    }
    #pragma unroll
    for (int j = 0; j < 8; j++) s_acc[wid * 256 + lane + 32 * j] = accl[j];
    __syncthreads();
    {
        float v = 0.f;
        #pragma unroll
        for (int w = 0; w < 8; w++) v += s_acc[w * 256 + tid];
        s_spa[tid] = v;                   // stays in smem
    }
    __syncthreads();

    // ---- phase B: fused 1x1 conv + BN + ReLU (16 outputs x 4 pixels / thread) ----
    int opart = tid >> 6;                 // 0..3: output channels [opart*16, +16)
    int pixg  = tid & 63;                 // 4 pixels: pixg*4 .. +3 within row
    int prow  = (blk & 255) * 256;        // row base in batch plane
    int p0    = prow + pixg * 4;
    int obase = opart * 16;

    unsigned long long acc[32];           // [j(0..7 output-pairs)][k(0..3 pixels)]
    #pragma unroll
    for (int j = 0; j < 32; j++) acc[j] = 0ull;

    const float4* xb = (const float4*)(x2 + (size_t)b * C2N * NPIX2 + p0);
    for (int c = 0; c < 64; c++) {
        float4 xv = xb[(size_t)c << 14];  // NPIX2/4 float4s per channel
        unsigned long long xp[4];
        asm("mov.b64 %0, {%1, %1};" : "=l"(xp[0]) : "f"(xv.x));
        asm("mov.b64 %0, {%1, %1};" : "=l"(xp[1]) : "f"(xv.y));
        asm("mov.b64 %0, {%1, %1};" : "=l"(xp[2]) : "f"(xv.z));
        asm("mov.b64 %0, {%1, %1};" : "=l"(xp[3]) : "f"(xv.w));
        const ulonglong2* wc = (const ulonglong2*)&s_w[(c << 6) + obase];
        #pragma unroll
        for (int h = 0; h < 4; h++) {     // 2 output-pairs per ulonglong2
            ulonglong2 w = wc[h];
            #pragma unroll
            for (int k = 0; k < 4; k++) {
                asm("fma.rn.f32x2 %0, %1, %2, %0;" : "+l"(acc[(2*h+0)*4 + k]) : "l"(w.x), "l"(xp[k]));
                asm("fma.rn.f32x2 %0, %1, %2, %0;" : "+l"(acc[(2*h+1)*4 + k]) : "l"(w.y), "l"(xp[k]));
            }
        }
    }
    float4 sv = ((const float4*)s_spa)[pixg];
    float svk[4] = {sv.x, sv.y, sv.z, sv.w};
    float* ob = out + (size_t)b * C2N * NPIX2 + p0;
    #pragma unroll
    for (int j = 0; j < 8; j++) {
        int o0 = obase + 2 * j, o1 = o0 + 1;
        float s30 = s_s3[o0], t30 = s_t3[o0];
        float s31 = s_s3[o1], t31 = s_t3[o1];
        float r0[4], r1[4];
        #pragma unroll
        for (int k = 0; k < 4; k++) {
            float lo, hi;
            asm("mov.b64 {%0, %1}, %2;" : "=f"(lo), "=f"(hi) : "l"(acc[j * 4 + k]));
            r0[k] = fmaxf(fmaf(s30, svk[k], lo) + t30, 0.f);
            r1[k] = fmaxf(fmaf(s31, svk[k], hi) + t31, 0.f);
        }
        ((float4*)(ob + ((size_t)o0 << 16)))[0] = make_float4(r0[0], r0[1], r0[2], r0[3]);
        ((float4*)(ob + ((size_t)o1 << 16)))[0] = make_float4(r1[0], r1[1], r1[2], r1[3]);
    }
}

extern "C" void kernel_launch(void* const* d_in, const int* in_sizes, int n_in,
                              void* d_out, int out_size) {
    const float* x1    = (const float*)d_in[0];
    const float* x2    = (const float*)d_in[1];
    const float* wc1   = (const float*)d_in[2];
    const float* bc1   = (const float*)d_in[3];
    const float* wc2   = (const float*)d_in[4];
    const float* bc2   = (const float*)d_in[5];
    const float* wp1   = (const float*)d_in[6];
    const float* bp1   = (const float*)d_in[7];
    const float* wp2   = (const float*)d_in[8];
    const float* bp2   = (const float*)d_in[9];
    const float* wlin  = (const float*)d_in[10];
    const float* blin  = (const float*)d_in[11];
    const float* wf    = (const float*)d_in[12];
    const float* bf    = (const float*)d_in[13];
    const float* gamma = (const float*)d_in[14];
    const float* beta  = (const float*)d_in[15];
    float* out = (float*)d_out;

    k_pos    <<<256 + 1024, 256>>>(x1, wp1, bp1, x2, wp2, bp2);
    k_w3     <<<16, 256>>>(wc1, bc1, wc2, bc2, wf, bf, gamma, beta);
    k_spafuse<<<BATCH * NB, 256>>>(wlin, blin, x2, out);
}

// round 9
// speedup vs baseline: 1.1217x; 1.0212x over previous
#include <cuda_runtime.h>

#define BATCH 4
#define C1N 128
#define C2N 64
#define NPIX1 16384   // 128*128
#define NPIX2 65536   // 256*256
#define NB 256

// ---- scratch (device globals; zero-init at load; k_fuse re-zeroes g_gaps) ----
__device__ float g_gaps[BATCH * C1N + BATCH * C2N];  // [0,512): x1 sums, [512,768): x2 sums
__device__ __align__(16) float g_pos1[BATCH * NB * 64];   // [b][n][ij]
__device__ __align__(16) float g_pos2[BATCH * NB * 256];  // [b][n][ij]
__device__ __align__(16) float g_spa [BATCH * NPIX2];     // [b][h=n][w=k]
__device__ __align__(16) float g_w3t [BATCH * C2N * C2N]; // [b][c][o]  prefused, transposed
__device__ __align__(16) float g_s3  [C2N];
__device__ __align__(16) float g_t3  [C2N];

__device__ __forceinline__ float ex2f(float x) {   // guaranteed MUFU.EX2
    float r;
    asm("ex2.approx.ftz.f32 %0, %1;" : "=f"(r) : "f"(x));
    return r;
}

// ---- kernel 1: pos1 & pos2 + channel sums; NO in-loop reductions ----
__global__ void __launch_bounds__(256) k_pos(const float* __restrict__ x1,
                                             const float* __restrict__ wp1,
                                             const float* __restrict__ bp1,
                                             const float* __restrict__ x2,
                                             const float* __restrict__ wp2,
                                             const float* __restrict__ bp2) {
    __shared__ __align__(16) float part[8][256];
    __shared__ float cpart[8][16][33];   // padded: conflict-free column reads
    int tid = threadIdx.x, wid = tid >> 5, lane = tid & 31;

    if (blockIdx.x < 256) {
        // ---- pos1: warp owns 16 channels x 256 pixels ----
        int bid = blockIdx.x;
        int b = bid >> 6;
        int p0 = (bid & 63) << 8;
        const float* plane = x1 + (size_t)b * C1N * NPIX1 + p0;
        float d[8];
        #pragma unroll
        for (int k = 0; k < 8; k++) d[k] = 0.f;
        float cs[16];
        #pragma unroll 8
        for (int j = 0; j < 16; j++) {
            int c = wid + 8 * j;
            float w = __ldg(&wp1[c]);
            const float4* cp = (const float4*)(plane + ((size_t)c << 14));
            float4 v0 = cp[lane];
            float4 v1 = cp[lane + 32];
            d[0] = fmaf(w, v0.x, d[0]); d[1] = fmaf(w, v0.y, d[1]);
            d[2] = fmaf(w, v0.z, d[2]); d[3] = fmaf(w, v0.w, d[3]);
            d[4] = fmaf(w, v1.x, d[4]); d[5] = fmaf(w, v1.y, d[5]);
            d[6] = fmaf(w, v1.z, d[6]); d[7] = fmaf(w, v1.w, d[7]);
            cs[j] = ((v0.x + v0.y) + (v0.z + v0.w)) + ((v1.x + v1.y) + (v1.z + v1.w));
        }
        #pragma unroll
        for (int j = 0; j < 16; j++) cpart[wid][j][lane] = cs[j];
        ((float4*)&part[wid][lane * 4])[0]       = make_float4(d[0], d[1], d[2], d[3]);
        ((float4*)&part[wid][128 + lane * 4])[0] = make_float4(d[4], d[5], d[6], d[7]);
        __syncthreads();
        float dot = bp1[0];
        #pragma unroll
        for (int w = 0; w < 8; w++) dot += part[w][tid];
        int p = p0 + tid;
        int y = p >> 7, x = p & 127;
        int n  = ((y >> 3) << 4) | (x >> 3);
        int ij = ((y & 7) << 3) | (x & 7);
        g_pos1[((b << 8) | n) * 64 + ij] = dot;
        if (tid < 128) {                 // channel-sum reduce: thread owns (warp, j)
            int w = tid >> 4, j = tid & 15;
            float s = 0.f;
            #pragma unroll
            for (int l = 0; l < 32; l++) s += cpart[w][j][l];
            atomicAdd(&g_gaps[b * C1N + w + 8 * j], s);
        }
    } else {
        // ---- pos2: warp owns 8 channels x 256 pixels ----
        int bid = blockIdx.x - 256;
        int b = bid >> 8;
        int p0 = (bid & 255) << 8;
        const float* plane = x2 + (size_t)b * C2N * NPIX2 + p0;
        float d[8];
        #pragma unroll
        for (int k = 0; k < 8; k++) d[k] = 0.f;
        float cs[8];
        #pragma unroll
        for (int j = 0; j < 8; j++) {
            int c = wid + 8 * j;
            float w = __ldg(&wp2[c]);
            const float4* cp = (const float4*)(plane + ((size_t)c << 16));
            float4 v0 = cp[lane];
            float4 v1 = cp[lane + 32];
            d[0] = fmaf(w, v0.x, d[0]); d[1] = fmaf(w, v0.y, d[1]);
            d[2] = fmaf(w, v0.z, d[2]); d[3] = fmaf(w, v0.w, d[3]);
            d[4] = fmaf(w, v1.x, d[4]); d[5] = fmaf(w, v1.y, d[5]);
            d[6] = fmaf(w, v1.z, d[6]); d[7] = fmaf(w, v1.w, d[7]);
            cs[j] = ((v0.x + v0.y) + (v0.z + v0.w)) + ((v1.x + v1.y) + (v1.z + v1.w));
        }
        #pragma unroll
        for (int j = 0; j < 8; j++) cpart[wid][j][lane] = cs[j];
        ((float4*)&part[wid][lane * 4])[0]       = make_float4(d[0], d[1], d[2], d[3]);
        ((float4*)&part[wid][128 + lane * 4])[0] = make_float4(d[4], d[5], d[6], d[7]);
        __syncthreads();
        float dot = bp2[0];
        #pragma unroll
        for (int w = 0; w < 8; w++) dot += part[w][tid];
        int p = p0 + tid;
        int y = p >> 8, x = p & 255;
        int n  = ((y >> 4) << 4) | (x >> 4);
        int ij = ((y & 15) << 4) | (x & 15);
        g_pos2[((b << 8) | n) * 256 + ij] = dot;
        if (tid < 64) {
            int w = tid >> 3, j = tid & 7;
            float s = 0.f;
            #pragma unroll
            for (int l = 0; l < 32; l++) s += cpart[w][j][l];
            atomicAdd(&g_gaps[BATCH * C1N + b * C2N + w + 8 * j], s);
        }
    }
}

// ---- kernel 2: mlp -> cw softmax (redundant per CTA) -> prefused w3t/s3/t3 ----
__global__ void __launch_bounds__(256) k_w3(const float* __restrict__ wc1, const float* __restrict__ bc1,
                                            const float* __restrict__ wc2, const float* __restrict__ bc2,
                                            const float* __restrict__ wf,  const float* __restrict__ bf,
                                            const float* __restrict__ gamma, const float* __restrict__ beta) {
    __shared__ float s_m1[256], s_m2[256], s_cw[256];
    int t = threadIdx.x;
    int b = t >> 6, g = (t >> 3) & 7, o = t & 7;
    const float INV1 = 1.f / NPIX1, INV2 = 1.f / NPIX2;
    {
        float a = bc1[o];
        const float* gp = &g_gaps[b * C1N + g * 16];
        #pragma unroll
        for (int c = 0; c < 16; c++) a = fmaf(wc1[o * 16 + c] * INV1, gp[c], a);
        s_m1[t] = fmaxf(a, 0.f);
    }
    {
        float a = bc2[o];
        const float* gp = &g_gaps[BATCH * C1N + b * C2N + g * 8];
        #pragma unroll
        for (int c = 0; c < 8; c++) a = fmaf(wc2[o * 8 + c] * INV2, gp[c], a);
        s_m2[t] = fmaxf(a, 0.f);
    }
    __syncthreads();
    if (t < 32) {
        int bb = t >> 3, gg = t & 7;
        int base = bb * 64 + gg * 8;
        float nr = 0.f;
        #pragma unroll
        for (int j = 0; j < 8; j++) { float m = s_m2[base + j]; nr += m * m; }
        float lg[8]; float mx = -1e30f;
        #pragma unroll
        for (int j = 0; j < 8; j++) { lg[j] = s_m1[base + j] * nr; mx = fmaxf(mx, lg[j]); }
        float Z = 0.f;
        #pragma unroll
        for (int j = 0; j < 8; j++) { lg[j] = expf(lg[j] - mx); Z += lg[j]; }
        float iz = 1.f / Z;
        #pragma unroll
        for (int j = 0; j < 8; j++) s_cw[base + j] = lg[j] * iz;
    }
    __syncthreads();
    const float A = rsqrtf(1.f + 1e-5f);
    #pragma unroll
    for (int k = 0; k < 4; k++) {            // this CTA's 1024-elem slice of [b][c][o]
        int i = blockIdx.x * 1024 + k * 256 + t;
        int bb = i >> 12, co = i & 4095, cc = co >> 6, oo = co & 63;
        g_w3t[i] = gamma[oo] * A * wf[oo * 64 + cc] * s_cw[bb * 64 + cc];
    }
    if (blockIdx.x == 0 && t < 64) {
        float ws = 0.f;
        for (int c = 0; c < 64; c++) ws += wf[t * 64 + c];
        float Ao = gamma[t] * A;
        g_s3[t] = Ao * ws;
        g_t3[t] = Ao * bf[t] + beta[t];
    }
}

// ---- kernel 3: per-block spatial attention (lean registers, high occupancy) ----
__global__ void __launch_bounds__(256) k_spa(const float* __restrict__ wlin,
                                             const float* __restrict__ blin) {
    __shared__ __align__(16) float s_p1[64];
    __shared__ float s_x1t[256], s_p2[256], s_red[18];
    __shared__ float s_acc[8 * 256];
    const float LOG2E = 1.4426950408889634f;
    int tid = threadIdx.x, wid = tid >> 5, lane = tid & 31;
    int blk = blockIdx.x;                 // = b*256 + n
    if (tid < 64) s_p1[tid] = g_pos1[blk * 64 + tid];
    s_p2[tid] = g_pos2[blk * 256 + tid];
    __syncthreads();
    float acc_t = blin[tid];
    const float4* wr = (const float4*)(wlin + tid * 64);
    #pragma unroll
    for (int c4 = 0; c4 < 16; c4++) {
        float4 w = wr[c4];
        acc_t += w.x * s_p1[c4 * 4 + 0] + w.y * s_p1[c4 * 4 + 1]
               + w.z * s_p1[c4 * 4 + 2] + w.w * s_p1[c4 * 4 + 3];
    }
    acc_t *= LOG2E;                       // exp(z) = exp2(z*log2e)
    s_x1t[tid] = acc_t;
    float vmax = acc_t, vmin = acc_t;
    #pragma unroll
    for (int o = 16; o; o >>= 1) {
        vmax = fmaxf(vmax, __shfl_xor_sync(0xffffffffu, vmax, o));
        vmin = fminf(vmin, __shfl_xor_sync(0xffffffffu, vmin, o));
    }
    if (lane == 0) { s_red[wid] = vmax; s_red[8 + wid] = vmin; }
    __syncthreads();
    if (tid == 0) {
        float mx = s_red[0], mn = s_red[8];
        #pragma unroll
        for (int w = 1; w < 8; w++) { mx = fmaxf(mx, s_red[w]); mn = fminf(mn, s_red[8 + w]); }
        s_red[16] = mx; s_red[17] = mn;
    }
    __syncthreads();
    float xmax = s_red[16], xmin = s_red[17];

    float x1r[8];
    #pragma unroll
    for (int j = 0; j < 8; j++) x1r[j] = s_x1t[lane + 32 * j];

    float accl[8];
    #pragma unroll
    for (int j = 0; j < 8; j++) accl[j] = 0.f;

    #pragma unroll 2
    for (int q = wid; q < 256; q += 8) {
        float p = s_p2[q];
        float rm = (p >= 0.f) ? p * xmax : p * xmin;   // exact row max (log2 domain)
        float e[8]; float sum = 0.f;
        #pragma unroll
        for (int j = 0; j < 8; j++) {
            float v = ex2f(fmaf(p, x1r[j], -rm));      // single MUFU.EX2
            e[j] = v; sum += v;
        }
        #pragma unroll
        for (int o = 16; o; o >>= 1) sum += __shfl_xor_sync(0xffffffffu, sum, o);
        float coef = __fdividef(p, sum);
        #pragma unroll
        for (int j = 0; j < 8; j++) accl[j] = fmaf(coef, e[j], accl[j]);
    }
    #pragma unroll
    for (int j = 0; j < 8; j++) s_acc[wid * 256 + lane + 32 * j] = accl[j];
    __syncthreads();
    float v = 0.f;
    #pragma unroll
    for (int w = 0; w < 8; w++) v += s_acc[w * 256 + tid];
    g_spa[blk * 256 + tid] = v;
}

// ---- kernel 4: fused 1x1 conv + BN + ReLU; 8 outputs x 4 pixels / thread ----
// grid = b*512 + n*2 + half. CTA covers 128 pixels of output row n.
__global__ void __launch_bounds__(256) k_fuse(const float* __restrict__ x2,
                                              float* __restrict__ out) {
    __shared__ __align__(16) float s_w[C2N * C2N];   // [c][o]
    __shared__ float s_s3[64], s_t3[64];
    int tid = threadIdx.x;
    int blk = blockIdx.x;
    int b    = blk >> 9;
    int n    = (blk >> 1) & 255;
    int half = blk & 1;
    int opart = tid >> 5;                // 0..7: outputs [opart*8, +8)
    int pixg  = tid & 31;                // pixels pixg*4 .. +3 (within half-row)
    int p0 = n * 256 + half * 128 + pixg * 4;
    int obase = opart * 8;

    // re-zero the gap accumulators for the next graph replay
    if (blk < 3) {
        int i = blk * 256 + tid;
        if (i < BATCH * C1N + BATCH * C2N) g_gaps[i] = 0.f;
    }

    {
        const float4* gw = (const float4*)&g_w3t[b * 4096];
        float4* swv = (float4*)s_w;
        #pragma unroll
        for (int k = 0; k < 4; k++) swv[k * 256 + tid] = gw[k * 256 + tid];
        if (tid < 64) { s_s3[tid] = g_s3[tid]; s_t3[tid] = g_t3[tid]; }
    }
    __syncthreads();

    unsigned long long acc[16];          // [j(0..3 output-pairs)][k(0..3 pixels)]
    #pragma unroll
    for (int j = 0; j < 16; j++) acc[j] = 0ull;

    const float4* xb = (const float4*)(x2 + (size_t)b * C2N * NPIX2 + p0);
    for (int c = 0; c < 64; c++) {
        float4 xv = xb[(size_t)c << 14];
        unsigned long long xp[4];
        asm("mov.b64 %0, {%1, %1};" : "=l"(xp[0]) : "f"(xv.x));
        asm("mov.b64 %0, {%1, %1};" : "=l"(xp[1]) : "f"(xv.y));
        asm("mov.b64 %0, {%1, %1};" : "=l"(xp[2]) : "f"(xv.z));
        asm("mov.b64 %0, {%1, %1};" : "=l"(xp[3]) : "f"(xv.w));
        const ulonglong2* wc = (const ulonglong2*)&s_w[(c << 6) + obase];
        ulonglong2 w0 = wc[0];           // outputs obase+0..3
        ulonglong2 w1 = wc[1];           // outputs obase+4..7
        #pragma unroll
        for (int k = 0; k < 4; k++) {
            asm("fma.rn.f32x2 %0, %1, %2, %0;" : "+l"(acc[0 * 4 + k]) : "l"(w0.x), "l"(xp[k]));
            asm("fma.rn.f32x2 %0, %1, %2, %0;" : "+l"(acc[1 * 4 + k]) : "l"(w0.y), "l"(xp[k]));
            asm("fma.rn.f32x2 %0, %1, %2, %0;" : "+l"(acc[2 * 4 + k]) : "l"(w1.x), "l"(xp[k]));
            asm("fma.rn.f32x2 %0, %1, %2, %0;" : "+l"(acc[3 * 4 + k]) : "l"(w1.y), "l"(xp[k]));
        }
    }
    float4 sv = *(const float4*)&g_spa[(size_t)b * NPIX2 + p0];
    float svk[4] = {sv.x, sv.y, sv.z, sv.w};
    float* ob = out + (size_t)b * C2N * NPIX2 + p0;
    #pragma unroll
    for (int j = 0; j < 4; j++) {
        int o0 = obase + 2 * j, o1 = o0 + 1;
        float s30 = s_s3[o0], t30 = s_t3[o0];
        float s31 = s_s3[o1], t31 = s_t3[o1];
        float r0[4], r1[4];
        #pragma unroll
        for (int k = 0; k < 4; k++) {
            float lo, hi;
            asm("mov.b64 {%0, %1}, %2;" : "=f"(lo), "=f"(hi) : "l"(acc[j * 4 + k]));
            r0[k] = fmaxf(fmaf(s30, svk[k], lo) + t30, 0.f);
            r1[k] = fmaxf(fmaf(s31, svk[k], hi) + t31, 0.f);
        }
        ((float4*)(ob + ((size_t)o0 << 16)))[0] = make_float4(r0[0], r0[1], r0[2], r0[3]);
        ((float4*)(ob + ((size_t)o1 << 16)))[0] = make_float4(r1[0], r1[1], r1[2], r1[3]);
    }
}

extern "C" void kernel_launch(void* const* d_in, const int* in_sizes, int n_in,
                              void* d_out, int out_size) {
    const float* x1    = (const float*)d_in[0];
    const float* x2    = (const float*)d_in[1];
    const float* wc1   = (const float*)d_in[2];
    const float* bc1   = (const float*)d_in[3];
    const float* wc2   = (const float*)d_in[4];
    const float* bc2   = (const float*)d_in[5];
    const float* wp1   = (const float*)d_in[6];
    const float* bp1   = (const float*)d_in[7];
    const float* wp2   = (const float*)d_in[8];
    const float* bp2   = (const float*)d_in[9];
    const float* wlin  = (const float*)d_in[10];
    const float* blin  = (const float*)d_in[11];
    const float* wf    = (const float*)d_in[12];
    const float* bf    = (const float*)d_in[13];
    const float* gamma = (const float*)d_in[14];
    const float* beta  = (const float*)d_in[15];
    float* out = (float*)d_out;

    k_pos <<<256 + 1024, 256>>>(x1, wp1, bp1, x2, wp2, bp2);
    k_w3  <<<16, 256>>>(wc1, bc1, wc2, bc2, wf, bf, gamma, beta);
    k_spa <<<BATCH * NB, 256>>>(wlin, blin);
    k_fuse<<<BATCH * NB * 2, 256>>>(x2, out);
}

// round 10
// speedup vs baseline: 1.2648x; 1.1276x over previous
#include <cuda_runtime.h>

#define BATCH 4
#define C1N 128
#define C2N 64
#define NPIX1 16384   // 128*128
#define NPIX2 65536   // 256*256
#define NB 256

// ---- scratch (device globals; zero-init at load; k_fuse re-zeroes g_gaps) ----
__device__ float g_gaps[BATCH * C1N + BATCH * C2N];  // [0,512): x1 sums, [512,768): x2 sums
__device__ __align__(16) float g_pos1[BATCH * NB * 64];   // [b][n][ij]
__device__ __align__(16) float g_pos2[BATCH * NB * 256];  // [b][n][ij]
__device__ __align__(16) float g_spa [BATCH * NPIX2];     // [b][h=n][w=k]
__device__ __align__(16) float g_w3t [BATCH * C2N * C2N]; // [b][c][o]  prefused, transposed
__device__ __align__(16) float g_s3  [C2N];
__device__ __align__(16) float g_t3  [C2N];

__device__ __forceinline__ float ex2f(float x) {   // guaranteed MUFU.EX2
    float r;
    asm("ex2.approx.ftz.f32 %0, %1;" : "=f"(r) : "f"(x));
    return r;
}

// ---- kernel 1: pos1 & pos2 + channel sums; NO in-loop reductions ----
__global__ void __launch_bounds__(256) k_pos(const float* __restrict__ x1,
                                             const float* __restrict__ wp1,
                                             const float* __restrict__ bp1,
                                             const float* __restrict__ x2,
                                             const float* __restrict__ wp2,
                                             const float* __restrict__ bp2) {
    __shared__ __align__(16) float part[8][256];
    __shared__ float cpart[8][16][33];   // padded: conflict-free column reads
    int tid = threadIdx.x, wid = tid >> 5, lane = tid & 31;

    if (blockIdx.x < 256) {
        // ---- pos1: warp owns 16 channels x 256 pixels ----
        int bid = blockIdx.x;
        int b = bid >> 6;
        int p0 = (bid & 63) << 8;
        const float* plane = x1 + (size_t)b * C1N * NPIX1 + p0;
        float d[8];
        #pragma unroll
        for (int k = 0; k < 8; k++) d[k] = 0.f;
        float cs[16];
        #pragma unroll 8
        for (int j = 0; j < 16; j++) {
            int c = wid + 8 * j;
            float w = __ldg(&wp1[c]);
            const float4* cp = (const float4*)(plane + ((size_t)c << 14));
            float4 v0 = cp[lane];
            float4 v1 = cp[lane + 32];
            d[0] = fmaf(w, v0.x, d[0]); d[1] = fmaf(w, v0.y, d[1]);
            d[2] = fmaf(w, v0.z, d[2]); d[3] = fmaf(w, v0.w, d[3]);
            d[4] = fmaf(w, v1.x, d[4]); d[5] = fmaf(w, v1.y, d[5]);
            d[6] = fmaf(w, v1.z, d[6]); d[7] = fmaf(w, v1.w, d[7]);
            cs[j] = ((v0.x + v0.y) + (v0.z + v0.w)) + ((v1.x + v1.y) + (v1.z + v1.w));
        }
        #pragma unroll
        for (int j = 0; j < 16; j++) cpart[wid][j][lane] = cs[j];
        ((float4*)&part[wid][lane * 4])[0]       = make_float4(d[0], d[1], d[2], d[3]);
        ((float4*)&part[wid][128 + lane * 4])[0] = make_float4(d[4], d[5], d[6], d[7]);
        __syncthreads();
        float dot = bp1[0];
        #pragma unroll
        for (int w = 0; w < 8; w++) dot += part[w][tid];
        int p = p0 + tid;
        int y = p >> 7, x = p & 127;
        int n  = ((y >> 3) << 4) | (x >> 3);
        int ij = ((y & 7) << 3) | (x & 7);
        g_pos1[((b << 8) | n) * 64 + ij] = dot;
        if (tid < 128) {                 // channel-sum reduce: thread owns (warp, j)
            int w = tid >> 4, j = tid & 15;
            float s = 0.f;
            #pragma unroll
            for (int l = 0; l < 32; l++) s += cpart[w][j][l];
            atomicAdd(&g_gaps[b * C1N + w + 8 * j], s);
        }
    } else {
        // ---- pos2: warp owns 8 channels x 256 pixels ----
        int bid = blockIdx.x - 256;
        int b = bid >> 8;
        int p0 = (bid & 255) << 8;
        const float* plane = x2 + (size_t)b * C2N * NPIX2 + p0;
        float d[8];
        #pragma unroll
        for (int k = 0; k < 8; k++) d[k] = 0.f;
        float cs[8];
        #pragma unroll
        for (int j = 0; j < 8; j++) {
            int c = wid + 8 * j;
            float w = __ldg(&wp2[c]);
            const float4* cp = (const float4*)(plane + ((size_t)c << 16));
            float4 v0 = cp[lane];
            float4 v1 = cp[lane + 32];
            d[0] = fmaf(w, v0.x, d[0]); d[1] = fmaf(w, v0.y, d[1]);
            d[2] = fmaf(w, v0.z, d[2]); d[3] = fmaf(w, v0.w, d[3]);
            d[4] = fmaf(w, v1.x, d[4]); d[5] = fmaf(w, v1.y, d[5]);
            d[6] = fmaf(w, v1.z, d[6]); d[7] = fmaf(w, v1.w, d[7]);
            cs[j] = ((v0.x + v0.y) + (v0.z + v0.w)) + ((v1.x + v1.y) + (v1.z + v1.w));
        }
        #pragma unroll
        for (int j = 0; j < 8; j++) cpart[wid][j][lane] = cs[j];
        ((float4*)&part[wid][lane * 4])[0]       = make_float4(d[0], d[1], d[2], d[3]);
        ((float4*)&part[wid][128 + lane * 4])[0] = make_float4(d[4], d[5], d[6], d[7]);
        __syncthreads();
        float dot = bp2[0];
        #pragma unroll
        for (int w = 0; w < 8; w++) dot += part[w][tid];
        int p = p0 + tid;
        int y = p >> 8, x = p & 255;
        int n  = ((y >> 4) << 4) | (x >> 4);
        int ij = ((y & 15) << 4) | (x & 15);
        g_pos2[((b << 8) | n) * 256 + ij] = dot;
        if (tid < 64) {
            int w = tid >> 3, j = tid & 7;
            float s = 0.f;
            #pragma unroll
            for (int l = 0; l < 32; l++) s += cpart[w][j][l];
            atomicAdd(&g_gaps[BATCH * C1N + b * C2N + w + 8 * j], s);
        }
    }
}

// ---- kernel 2: mlp -> cw softmax (redundant per CTA) -> prefused w3t/s3/t3 ----
__global__ void __launch_bounds__(256) k_w3(const float* __restrict__ wc1, const float* __restrict__ bc1,
                                            const float* __restrict__ wc2, const float* __restrict__ bc2,
                                            const float* __restrict__ wf,  const float* __restrict__ bf,
                                            const float* __restrict__ gamma, const float* __restrict__ beta) {
    __shared__ float s_m1[256], s_m2[256], s_cw[256];
    int t = threadIdx.x;
    int b = t >> 6, g = (t >> 3) & 7, o = t & 7;
    const float INV1 = 1.f / NPIX1, INV2 = 1.f / NPIX2;
    {
        float a = bc1[o];
        const float* gp = &g_gaps[b * C1N + g * 16];
        #pragma unroll
        for (int c = 0; c < 16; c++) a = fmaf(wc1[o * 16 + c] * INV1, gp[c], a);
        s_m1[t] = fmaxf(a, 0.f);
    }
    {
        float a = bc2[o];
        const float* gp = &g_gaps[BATCH * C1N + b * C2N + g * 8];
        #pragma unroll
        for (int c = 0; c < 8; c++) a = fmaf(wc2[o * 8 + c] * INV2, gp[c], a);
        s_m2[t] = fmaxf(a, 0.f);
    }
    __syncthreads();
    if (t < 32) {
        int bb = t >> 3, gg = t & 7;
        int base = bb * 64 + gg * 8;
        float nr = 0.f;
        #pragma unroll
        for (int j = 0; j < 8; j++) { float m = s_m2[base + j]; nr += m * m; }
        float lg[8]; float mx = -1e30f;
        #pragma unroll
        for (int j = 0; j < 8; j++) { lg[j] = s_m1[base + j] * nr; mx = fmaxf(mx, lg[j]); }
        float Z = 0.f;
        #pragma unroll
        for (int j = 0; j < 8; j++) { lg[j] = expf(lg[j] - mx); Z += lg[j]; }
        float iz = 1.f / Z;
        #pragma unroll
        for (int j = 0; j < 8; j++) s_cw[base + j] = lg[j] * iz;
    }
    __syncthreads();
    const float A = rsqrtf(1.f + 1e-5f);
    #pragma unroll
    for (int k = 0; k < 4; k++) {            // this CTA's 1024-elem slice of [b][c][o]
        int i = blockIdx.x * 1024 + k * 256 + t;
        int bb = i >> 12, co = i & 4095, cc = co >> 6, oo = co & 63;
        g_w3t[i] = gamma[oo] * A * wf[oo * 64 + cc] * s_cw[bb * 64 + cc];
    }
    if (blockIdx.x == 0 && t < 64) {
        float ws = 0.f;
        for (int c = 0; c < 64; c++) ws += wf[t * 64 + c];
        float Ao = gamma[t] * A;
        g_s3[t] = Ao * ws;
        g_t3[t] = Ao * bf[t] + beta[t];
    }
}

// ---- kernel 3: per-block spatial attention (lean registers, high occupancy) ----
__global__ void __launch_bounds__(256) k_spa(const float* __restrict__ wlin,
                                             const float* __restrict__ blin) {
    __shared__ __align__(16) float s_p1[64];
    __shared__ float s_x1t[256], s_p2[256], s_red[18];
    __shared__ float s_acc[8 * 256];
    const float LOG2E = 1.4426950408889634f;
    int tid = threadIdx.x, wid = tid >> 5, lane = tid & 31;
    int blk = blockIdx.x;                 // = b*256 + n
    if (tid < 64) s_p1[tid] = g_pos1[blk * 64 + tid];
    s_p2[tid] = g_pos2[blk * 256 + tid];
    __syncthreads();
    float acc_t = blin[tid];
    const float4* wr = (const float4*)(wlin + tid * 64);
    #pragma unroll
    for (int c4 = 0; c4 < 16; c4++) {
        float4 w = wr[c4];
        acc_t += w.x * s_p1[c4 * 4 + 0] + w.y * s_p1[c4 * 4 + 1]
               + w.z * s_p1[c4 * 4 + 2] + w.w * s_p1[c4 * 4 + 3];
    }
    acc_t *= LOG2E;                       // exp(z) = exp2(z*log2e)
    s_x1t[tid] = acc_t;
    float vmax = acc_t, vmin = acc_t;
    #pragma unroll
    for (int o = 16; o; o >>= 1) {
        vmax = fmaxf(vmax, __shfl_xor_sync(0xffffffffu, vmax, o));
        vmin = fminf(vmin, __shfl_xor_sync(0xffffffffu, vmin, o));
    }
    if (lane == 0) { s_red[wid] = vmax; s_red[8 + wid] = vmin; }
    __syncthreads();
    if (tid == 0) {
        float mx = s_red[0], mn = s_red[8];
        #pragma unroll
        for (int w = 1; w < 8; w++) { mx = fmaxf(mx, s_red[w]); mn = fminf(mn, s_red[8 + w]); }
        s_red[16] = mx; s_red[17] = mn;
    }
    __syncthreads();
    float xmax = s_red[16], xmin = s_red[17];

    float x1r[8];
    #pragma unroll
    for (int j = 0; j < 8; j++) x1r[j] = s_x1t[lane + 32 * j];

    float accl[8];
    #pragma unroll
    for (int j = 0; j < 8; j++) accl[j] = 0.f;

    #pragma unroll 2
    for (int q = wid; q < 256; q += 8) {
        float p = s_p2[q];
        float rm = (p >= 0.f) ? p * xmax : p * xmin;   // exact row max (log2 domain)
        float e[8]; float sum = 0.f;
        #pragma unroll
        for (int j = 0; j < 8; j++) {
            float v = ex2f(fmaf(p, x1r[j], -rm));      // single MUFU.EX2
            e[j] = v; sum += v;
        }
        #pragma unroll
        for (int o = 16; o; o >>= 1) sum += __shfl_xor_sync(0xffffffffu, sum, o);
        float coef = __fdividef(p, sum);
        #pragma unroll
        for (int j = 0; j < 8; j++) accl[j] = fmaf(coef, e[j], accl[j]);
    }
    #pragma unroll
    for (int j = 0; j < 8; j++) s_acc[wid * 256 + lane + 32 * j] = accl[j];
    __syncthreads();
    float v = 0.f;
    #pragma unroll
    for (int w = 0; w < 8; w++) v += s_acc[w * 256 + tid];
    g_spa[blk * 256 + tid] = v;
}

// ---- kernel 4: fused conv; pixel-pair packed FFMA2, duplicated weights ----
// grid = b*512 + n*2 + half. Thread = 8 outputs x 4 pixels; zero pack-movs in loop.
__global__ void __launch_bounds__(256) k_fuse(const float* __restrict__ x2,
                                              float* __restrict__ out) {
    __shared__ __align__(16) float s_wd[C2N * 128];  // [c][2o] duplicated weights (32KB)
    __shared__ float s_s3[64], s_t3[64];
    int tid = threadIdx.x;
    int blk = blockIdx.x;
    int b    = blk >> 9;
    int n    = (blk >> 1) & 255;
    int half = blk & 1;
    int opart = tid >> 5;                // warp-uniform: outputs [opart*8, +8)
    int pixg  = tid & 31;                // pixels pixg*4 .. +3 (within half-row)
    int p0 = n * 256 + half * 128 + pixg * 4;
    int obase = opart * 8;

    // re-zero the gap accumulators for the next graph replay
    if (blk < 3) {
        int i = blk * 256 + tid;
        if (i < BATCH * C1N + BATCH * C2N) g_gaps[i] = 0.f;
    }

    {   // build duplicated weight tile: each float4 of g_w3t -> two float4 of dups
        const float4* gw = (const float4*)&g_w3t[b * 4096];
        #pragma unroll
        for (int k = 0; k < 4; k++) {
            int g = k * 256 + tid;        // float4 index: c = g>>4, o4 = g&15
            float4 w = gw[g];
            float* dst = &s_wd[(g >> 4) * 128 + (g & 15) * 8];
            ((float4*)dst)[0] = make_float4(w.x, w.x, w.y, w.y);
            ((float4*)dst)[1] = make_float4(w.z, w.z, w.w, w.w);
        }
        if (tid < 64) { s_s3[tid] = g_s3[tid]; s_t3[tid] = g_t3[tid]; }
    }
    __syncthreads();

    unsigned long long acc[16];          // [o(0..7)][pixel-pair(0..1)]
    #pragma unroll
    for (int j = 0; j < 16; j++) acc[j] = 0ull;

    const double2* xb = (const double2*)(x2 + (size_t)b * C2N * NPIX2 + p0);
    #pragma unroll 2
    for (int c = 0; c < 64; c++) {
        double2 xv = xb[(size_t)c << 14];            // pixel pairs, already packed
        unsigned long long xp0 = __double_as_longlong(xv.x);
        unsigned long long xp1 = __double_as_longlong(xv.y);
        const double2* wd = (const double2*)&s_wd[c * 128 + obase * 2];
        double2 wv0 = wd[0], wv1 = wd[1], wv2 = wd[2], wv3 = wd[3];
        unsigned long long w[8] = {
            __double_as_longlong(wv0.x), __double_as_longlong(wv0.y),
            __double_as_longlong(wv1.x), __double_as_longlong(wv1.y),
            __double_as_longlong(wv2.x), __double_as_longlong(wv2.y),
            __double_as_longlong(wv3.x), __double_as_longlong(wv3.y)};
        #pragma unroll
        for (int o = 0; o < 8; o++) {
            asm("fma.rn.f32x2 %0, %1, %2, %0;" : "+l"(acc[2*o+0]) : "l"(w[o]), "l"(xp0));
            asm("fma.rn.f32x2 %0, %1, %2, %0;" : "+l"(acc[2*o+1]) : "l"(w[o]), "l"(xp1));
        }
    }
    float4 sv = *(const float4*)&g_spa[(size_t)b * NPIX2 + p0];
    float svk[4] = {sv.x, sv.y, sv.z, sv.w};
    float* ob = out + (size_t)b * C2N * NPIX2 + p0;
    #pragma unroll
    for (int o = 0; o < 8; o++) {
        int oo = obase + o;
        float s3 = s_s3[oo], t3 = s_t3[oo];
        float v0, v1, v2, v3;
        asm("mov.b64 {%0, %1}, %2;" : "=f"(v0), "=f"(v1) : "l"(acc[2*o+0]));
        asm("mov.b64 {%0, %1}, %2;" : "=f"(v2), "=f"(v3) : "l"(acc[2*o+1]));
        float r0 = fmaxf(fmaf(s3, svk[0], v0) + t3, 0.f);
        float r1 = fmaxf(fmaf(s3, svk[1], v1) + t3, 0.f);
        float r2 = fmaxf(fmaf(s3, svk[2], v2) + t3, 0.f);
        float r3 = fmaxf(fmaf(s3, svk[3], v3) + t3, 0.f);
        ((float4*)(ob + ((size_t)oo << 16)))[0] = make_float4(r0, r1, r2, r3);
    }
}

extern "C" void kernel_launch(void* const* d_in, const int* in_sizes, int n_in,
                              void* d_out, int out_size) {
    const float* x1    = (const float*)d_in[0];
    const float* x2    = (const float*)d_in[1];
    const float* wc1   = (const float*)d_in[2];
    const float* bc1   = (const float*)d_in[3];
    const float* wc2   = (const float*)d_in[4];
    const float* bc2   = (const float*)d_in[5];
    const float* wp1   = (const float*)d_in[6];
    const float* bp1   = (const float*)d_in[7];
    const float* wp2   = (const float*)d_in[8];
    const float* bp2   = (const float*)d_in[9];
    const float* wlin  = (const float*)d_in[10];
    const float* blin  = (const float*)d_in[11];
    const float* wf    = (const float*)d_in[12];
    const float* bf    = (const float*)d_in[13];
    const float* gamma = (const float*)d_in[14];
    const float* beta  = (const float*)d_in[15];
    float* out = (float*)d_out;

    k_pos <<<256 + 1024, 256>>>(x1, wp1, bp1, x2, wp2, bp2);
    k_w3  <<<16, 256>>>(wc1, bc1, wc2, bc2, wf, bf, gamma, beta);
    k_spa <<<BATCH * NB, 256>>>(wlin, blin);
    k_fuse<<<BATCH * NB * 2, 256>>>(x2, out);
}